// round 1
// baseline (speedup 1.0000x reference)
#include <cuda_runtime.h>

// CausalTrajectoryPrediction: per-node 4-layer MLP, fully fused.
// N=64 nodes, H=64, M=32, B=16384. One block = (node, 128-row batch tile).
// All weights for the node + all activations live in shared memory; each
// layer is a register-tiled GEMM. fp32 throughout (round-1 correctness
// baseline; FMA-pipe bound at ~64 FMA/cyc/SM).

namespace {
constexpr int kN = 64;        // nodes / input features
constexpr int kH = 64;        // hidden
constexpr int kM = 32;        // branch output
constexpr int kB = 16384;     // batch
constexpr int kBT = 128;      // batch tile per block
constexpr int kThreads = 256;

struct Smem {
    // Weights, row-padded to 68 floats (stride%32==4 -> conflict-free
    // per-k column reads; stride%4==0 -> float4-aligned row fills).
    float Wa[128][68];   // rows 0..63: W1a[i][h][n]; rows 64..127: W2a[i][h][n]
    float Wb[64][68];    // rows 0..31: W1b[i][m][h]; rows 32..63: W2b[i][m][h]
    float W3[64][68];    // W3a[i][h][k], k<64 (the r1|r2 part)
    // Activations, k-major, b-padded to 132 (16B-aligned float4 rows).
    float Xs[64][132];   // x tile transposed; row `node` zeroed (the mask)
    float Hs[128][132];  // layer-1 outputs (both branches); later reused for layer-3 out
    float Rs[64][132];   // feat = [r1(0..31) | r2(32..63)]
    float xi[128];       // x[b, node]
    float w3x[64];       // W3a[i][h][64+node]  (x2 rank-1 column)
    float b3a_s[64];
    float w3b_s[64];
    float b3b_s;
};
} // namespace

__global__ void __launch_bounds__(kThreads, 1)
ctp_fused_kernel(const float* __restrict__ x,
                 const float* __restrict__ W1a, const float* __restrict__ W1b,
                 const float* __restrict__ W2a, const float* __restrict__ W2b,
                 const float* __restrict__ W3a, const float* __restrict__ b3a,
                 const float* __restrict__ W3b, const float* __restrict__ b3b,
                 float* __restrict__ out)
{
    extern __shared__ char smem_raw[];
    Smem& s = *reinterpret_cast<Smem*>(smem_raw);
    const int tid   = threadIdx.x;
    const int node  = blockIdx.y;
    const int bbase = blockIdx.x * kBT;

    // ---------------- prologue: stage weights ----------------
    {
        const float* g1 = W1a + node * kH * kN;
        const float* g2 = W2a + node * kH * kN;
        for (int t = tid; t < 2048; t += kThreads) {      // 128 rows x 16 float4
            const int h  = t >> 4;
            const int n4 = (t & 15) << 2;
            const float* g = (h < kH) ? (g1 + h * kN + n4)
                                      : (g2 + (h - kH) * kN + n4);
            *reinterpret_cast<float4*>(&s.Wa[h][n4]) =
                *reinterpret_cast<const float4*>(g);
        }
        const float* gb1 = W1b + node * kM * kH;
        const float* gb2 = W2b + node * kM * kH;
        for (int t = tid; t < 1024; t += kThreads) {      // 64 rows x 16 float4
            const int c  = t >> 4;
            const int k4 = (t & 15) << 2;
            const float* g = (c < kM) ? (gb1 + c * kH + k4)
                                      : (gb2 + (c - kM) * kH + k4);
            *reinterpret_cast<float4*>(&s.Wb[c][k4]) =
                *reinterpret_cast<const float4*>(g);
        }
        const float* g3 = W3a + node * kH * 128;          // row stride 128 (2M+N)
        for (int t = tid; t < 1024; t += kThreads) {      // first 64 cols of each row
            const int h  = t >> 4;
            const int k4 = (t & 15) << 2;
            *reinterpret_cast<float4*>(&s.W3[h][k4]) =
                *reinterpret_cast<const float4*>(g3 + h * 128 + k4);
        }
        if (tid < 64) {
            s.w3x[tid]  = g3[tid * 128 + 64 + node];
            s.b3a_s[tid] = b3a[node * kH + tid];
            s.w3b_s[tid] = W3b[node * kH + tid];
        }
        if (tid == 0) s.b3b_s = b3b[node];
    }
    // ---------------- stage x tile transposed (k-major) ----------------
    {
        for (int t = tid; t < 2048; t += kThreads) {  // 128 rows x 16 float4
            const int b  = t & 127;                   // lanes differ in b -> conflict-free STS
            const int n4 = (t >> 7) << 2;
            const float4 v = *reinterpret_cast<const float4*>(
                x + (size_t)(bbase + b) * kN + n4);
            s.Xs[n4 + 0][b] = v.x;
            s.Xs[n4 + 1][b] = v.y;
            s.Xs[n4 + 2][b] = v.z;
            s.Xs[n4 + 3][b] = v.w;
        }
    }
    __syncthreads();

    // save x[:, node] and apply the off-diagonal mask (zero row `node`)
    if (tid < kBT) {
        s.xi[tid] = s.Xs[node][tid];
        s.Xs[node][tid] = 0.0f;
    }
    __syncthreads();

    // ---------------- layer 1 (both branches): Hs[128h][128b] ----------------
    // C[b, h] = sum_n Xs[n][b] * Wa[h][n], relu. 8x8 tile per thread.
    {
        const int b0 = (tid & 15) * 8;
        const int h0 = (tid >> 4) * 8;
        float acc[8][8];
        #pragma unroll
        for (int r = 0; r < 8; r++)
            #pragma unroll
            for (int c = 0; c < 8; c++) acc[r][c] = 0.0f;

        #pragma unroll 4
        for (int k = 0; k < kN; k++) {
            const float4 a0 = *reinterpret_cast<const float4*>(&s.Xs[k][b0]);
            const float4 a1 = *reinterpret_cast<const float4*>(&s.Xs[k][b0 + 4]);
            const float a[8] = {a0.x, a0.y, a0.z, a0.w, a1.x, a1.y, a1.z, a1.w};
            float w[8];
            #pragma unroll
            for (int c = 0; c < 8; c++) w[c] = s.Wa[h0 + c][k];
            #pragma unroll
            for (int r = 0; r < 8; r++)
                #pragma unroll
                for (int c = 0; c < 8; c++) acc[r][c] += a[r] * w[c];
        }
        #pragma unroll
        for (int c = 0; c < 8; c++) {
            float4 v0, v1;
            v0.x = fmaxf(acc[0][c], 0.f); v0.y = fmaxf(acc[1][c], 0.f);
            v0.z = fmaxf(acc[2][c], 0.f); v0.w = fmaxf(acc[3][c], 0.f);
            v1.x = fmaxf(acc[4][c], 0.f); v1.y = fmaxf(acc[5][c], 0.f);
            v1.z = fmaxf(acc[6][c], 0.f); v1.w = fmaxf(acc[7][c], 0.f);
            *reinterpret_cast<float4*>(&s.Hs[h0 + c][b0])     = v0;
            *reinterpret_cast<float4*>(&s.Hs[h0 + c][b0 + 4]) = v1;
        }
    }
    __syncthreads();

    // ---------------- layer 2 (both branches): Rs[64][128b] ----------------
    // Rs[c, b] = relu(sum_h Hs[base+h][b] * Wb[c][h]); c<32 branch1, else branch2.
    {
        const int b0 = (tid & 15) * 8;
        const int c0 = (tid >> 4) * 4;          // 0..60
        const int base = (c0 < kM) ? 0 : kH;    // which branch's hidden rows
        float acc[8][4];
        #pragma unroll
        for (int r = 0; r < 8; r++)
            #pragma unroll
            for (int c = 0; c < 4; c++) acc[r][c] = 0.0f;

        #pragma unroll 4
        for (int k = 0; k < kH; k++) {
            const float4 a0 = *reinterpret_cast<const float4*>(&s.Hs[base + k][b0]);
            const float4 a1 = *reinterpret_cast<const float4*>(&s.Hs[base + k][b0 + 4]);
            const float a[8] = {a0.x, a0.y, a0.z, a0.w, a1.x, a1.y, a1.z, a1.w};
            float w[4];
            #pragma unroll
            for (int c = 0; c < 4; c++) w[c] = s.Wb[c0 + c][k];
            #pragma unroll
            for (int r = 0; r < 8; r++)
                #pragma unroll
                for (int c = 0; c < 4; c++) acc[r][c] += a[r] * w[c];
        }
        #pragma unroll
        for (int c = 0; c < 4; c++) {
            float4 v0, v1;
            v0.x = fmaxf(acc[0][c], 0.f); v0.y = fmaxf(acc[1][c], 0.f);
            v0.z = fmaxf(acc[2][c], 0.f); v0.w = fmaxf(acc[3][c], 0.f);
            v1.x = fmaxf(acc[4][c], 0.f); v1.y = fmaxf(acc[5][c], 0.f);
            v1.z = fmaxf(acc[6][c], 0.f); v1.w = fmaxf(acc[7][c], 0.f);
            *reinterpret_cast<float4*>(&s.Rs[c0 + c][b0])     = v0;
            *reinterpret_cast<float4*>(&s.Rs[c0 + c][b0 + 4]) = v1;
        }
    }
    __syncthreads();

    // ---------------- layer 3: Hs[0..63][128b] (reuse) ----------------
    // h3[b,h] = relu(sum_k Rs[k][b]*W3[h][k] + xi[b]*w3x[h] + b3a[h])
    {
        const int b0 = (tid & 15) * 8;
        const int h0 = (tid >> 4) * 4;
        float acc[8][4];
        #pragma unroll
        for (int r = 0; r < 8; r++)
            #pragma unroll
            for (int c = 0; c < 4; c++) acc[r][c] = 0.0f;

        #pragma unroll 4
        for (int k = 0; k < 64; k++) {
            const float4 a0 = *reinterpret_cast<const float4*>(&s.Rs[k][b0]);
            const float4 a1 = *reinterpret_cast<const float4*>(&s.Rs[k][b0 + 4]);
            const float a[8] = {a0.x, a0.y, a0.z, a0.w, a1.x, a1.y, a1.z, a1.w};
            float w[4];
            #pragma unroll
            for (int c = 0; c < 4; c++) w[c] = s.W3[h0 + c][k];
            #pragma unroll
            for (int r = 0; r < 8; r++)
                #pragma unroll
                for (int c = 0; c < 4; c++) acc[r][c] += a[r] * w[c];
        }
        float xv[8];
        #pragma unroll
        for (int r = 0; r < 8; r++) xv[r] = s.xi[b0 + r];
        #pragma unroll
        for (int c = 0; c < 4; c++) {
            const float wx = s.w3x[h0 + c];
            const float bb = s.b3a_s[h0 + c];
            float v[8];
            #pragma unroll
            for (int r = 0; r < 8; r++)
                v[r] = fmaxf(acc[r][c] + xv[r] * wx + bb, 0.0f);
            *reinterpret_cast<float4*>(&s.Hs[h0 + c][b0]) =
                make_float4(v[0], v[1], v[2], v[3]);
            *reinterpret_cast<float4*>(&s.Hs[h0 + c][b0 + 4]) =
                make_float4(v[4], v[5], v[6], v[7]);
        }
    }
    __syncthreads();

    // ---------------- layer 4: out[b, node] ----------------
    if (tid < kBT) {
        const int b = tid;
        float acc = s.b3b_s;
        #pragma unroll 8
        for (int h = 0; h < kH; h++) acc += s.Hs[h][b] * s.w3b_s[h];
        out[(size_t)(bbase + b) * kN + node] = fmaxf(acc, 0.0f);
    }
}

extern "C" void kernel_launch(void* const* d_in, const int* in_sizes, int n_in,
                              void* d_out, int out_size)
{
    (void)in_sizes; (void)n_in; (void)out_size;
    const float* x   = (const float*)d_in[0];
    const float* W1a = (const float*)d_in[1];
    const float* W1b = (const float*)d_in[2];
    const float* W2a = (const float*)d_in[3];
    const float* W2b = (const float*)d_in[4];
    const float* W3a = (const float*)d_in[5];
    const float* b3a = (const float*)d_in[6];
    const float* W3b = (const float*)d_in[7];
    const float* b3b = (const float*)d_in[8];
    float* out = (float*)d_out;

    cudaFuncSetAttribute(ctp_fused_kernel,
                         cudaFuncAttributeMaxDynamicSharedMemorySize,
                         (int)sizeof(Smem));
    dim3 grid(kB / kBT, kN);   // 128 batch tiles x 64 nodes
    ctp_fused_kernel<<<grid, kThreads, sizeof(Smem)>>>(
        x, W1a, W1b, W2a, W2b, W3a, b3a, W3b, b3b, out);
}

// round 3
// speedup vs baseline: 2.9833x; 2.9833x over previous
#include <cuda_runtime.h>
#include <cstdint>

// CausalTrajectoryPrediction via portable tensor-core path:
// mma.sync.m16n8k8 tf32 (sm_80+ baseline PTX; tcgen05 is unavailable because
// the harness assembles for .target sm_103 without the 'a' feature set).
//
// Block = (node, 256-row batch tile), 256 threads = 8 warps.
// Each warp owns 32 batch rows for ALL layers -> activations stay in that
// warp's private smem rows; no block-level sync after staging.
//   L1: H1[256,128] = X[256,64]  @ [W1a;W2a]^T   (relu, tf32 store)
//   L2: H2[256,64]  = H1[256,128]@ [W1b|W2b]^T   (zero-padded concat, relu)
//   L3: D3[256,64]  = H2[256,64] @ W3a[:,0:64]^T
//   epi: h = relu(D3 + x_i*w3x + b3a);  out = relu(h . w3b + b3b)   (fp32)

namespace {
constexpr int kB       = 16384;
constexpr int kBT      = 256;     // batch rows per block
constexpr int kThreads = 256;     // 8 warps x 32 rows
constexpr int kAS      = 132;     // act row stride (floats): %32==4 -> conflict-free A frags

// smem byte offsets
constexpr uint32_t OFF_ACT = 0;                 // float [256][132]      = 135168
constexpr uint32_t OFF_BP1 = 135168;            // float2 [8][128][4]    =  32768
constexpr uint32_t OFF_BP2 = 167936;            // float2 [16][64][4]    =  32768
constexpr uint32_t OFF_BP3 = 200704;            // float2 [8][64][4]     =  16384
constexpr uint32_t OFF_XI  = 217088;            // float [256]
constexpr uint32_t OFF_W3X = 218112;            // float [64]
constexpr uint32_t OFF_B3A = 218368;            // float [64]
constexpr uint32_t OFF_W3B = 218624;            // float [64]
constexpr uint32_t OFF_B3B = 218880;            // float
constexpr uint32_t SMEM_BYTES = 218896;
} // namespace

__device__ __forceinline__ float f2tf(float f) {
    uint32_t u;
    asm("cvt.rna.tf32.f32 %0, %1;" : "=r"(u) : "f"(f));
    return __uint_as_float(u);
}

__device__ __forceinline__ void mma8(float d[4], const uint32_t a[4], const uint32_t b[2]) {
    asm volatile(
        "mma.sync.aligned.m16n8k8.row.col.f32.tf32.tf32.f32 "
        "{%0,%1,%2,%3}, {%4,%5,%6,%7}, {%8,%9}, {%0,%1,%2,%3};"
        : "+f"(d[0]), "+f"(d[1]), "+f"(d[2]), "+f"(d[3])
        : "r"(a[0]), "r"(a[1]), "r"(a[2]), "r"(a[3]), "r"(b[0]), "r"(b[1]));
}

// One warp-level GEMM: 32 rows (2 m16 tiles) x 64 cols (8 n8 tiles), K = 8*KSTEPS.
// A from act rows [r0, r0+32), cols [0, 8*KSTEPS).  B pre-paired in bp:
// bp[k8][n][kk] = float2(B[8k8+kk][n], B[8k8+kk+4][n]), n in [n0, n0+64).
template <int KSTEPS>
__device__ __forceinline__ void warp_gemm(float acc[2][8][4], const float* act,
                                          int r0, const float2* bp, int ncols,
                                          int n0, int tg, int t4) {
    #pragma unroll
    for (int mt = 0; mt < 2; mt++)
        #pragma unroll
        for (int nt = 0; nt < 8; nt++)
            #pragma unroll
            for (int i = 0; i < 4; i++) acc[mt][nt][i] = 0.0f;

    #pragma unroll
    for (int k8 = 0; k8 < KSTEPS; k8++) {
        uint32_t a0[4], a1[4];
        const float* p = act + (r0 + tg) * kAS + 8 * k8 + t4;
        a0[0] = __float_as_uint(p[0]);
        a0[2] = __float_as_uint(p[4]);
        a0[1] = __float_as_uint(p[8 * kAS]);
        a0[3] = __float_as_uint(p[8 * kAS + 4]);
        const float* q = p + 16 * kAS;
        a1[0] = __float_as_uint(q[0]);
        a1[2] = __float_as_uint(q[4]);
        a1[1] = __float_as_uint(q[8 * kAS]);
        a1[3] = __float_as_uint(q[8 * kAS + 4]);

        const float2* br = bp + (size_t)(k8 * ncols + n0 + tg) * 4 + t4;
        #pragma unroll
        for (int nt = 0; nt < 8; nt++) {
            const float2 bv = br[nt * 32];
            uint32_t b[2] = {__float_as_uint(bv.x), __float_as_uint(bv.y)};
            mma8(acc[0][nt], a0, b);
            mma8(acc[1][nt], a1, b);
        }
    }
}

// ReLU + tf32-round + store 32x64 accs into act cols [cbase, cbase+64)
__device__ __forceinline__ void store_relu(const float acc[2][8][4], float* act,
                                           int r0, int cbase, int tg, int t4) {
    #pragma unroll
    for (int mt = 0; mt < 2; mt++) {
        const int ru = r0 + 16 * mt + tg;
        #pragma unroll
        for (int nt = 0; nt < 8; nt++) {
            const int c0 = cbase + 8 * nt + 2 * t4;
            float2 v0 = make_float2(f2tf(fmaxf(acc[mt][nt][0], 0.f)),
                                    f2tf(fmaxf(acc[mt][nt][1], 0.f)));
            float2 v1 = make_float2(f2tf(fmaxf(acc[mt][nt][2], 0.f)),
                                    f2tf(fmaxf(acc[mt][nt][3], 0.f)));
            *reinterpret_cast<float2*>(act + ru * kAS + c0)       = v0;
            *reinterpret_cast<float2*>(act + (ru + 8) * kAS + c0) = v1;
        }
    }
}

__global__ void __launch_bounds__(kThreads)
ctp_mma_kernel(const float* __restrict__ x,
               const float* __restrict__ W1a, const float* __restrict__ W1b,
               const float* __restrict__ W2a, const float* __restrict__ W2b,
               const float* __restrict__ W3a, const float* __restrict__ b3a,
               const float* __restrict__ W3b, const float* __restrict__ b3b,
               float* __restrict__ out)
{
    extern __shared__ char smem[];
    float*  act   = reinterpret_cast<float*>(smem + OFF_ACT);
    float2* bp1   = reinterpret_cast<float2*>(smem + OFF_BP1);
    float2* bp2   = reinterpret_cast<float2*>(smem + OFF_BP2);
    float2* bp3   = reinterpret_cast<float2*>(smem + OFF_BP3);
    float*  xi    = reinterpret_cast<float*>(smem + OFF_XI);
    float*  w3x   = reinterpret_cast<float*>(smem + OFF_W3X);
    float*  b3a_s = reinterpret_cast<float*>(smem + OFF_B3A);
    float*  w3b_s = reinterpret_cast<float*>(smem + OFF_W3B);
    float*  b3b_s = reinterpret_cast<float*>(smem + OFF_B3B);

    const int tid   = threadIdx.x;
    const int node  = blockIdx.y;
    const int bbase = blockIdx.x * kBT;

    // ---------------- staging ----------------
    // X tile: mask col `node` to 0 (inputs_1), save x[:,node] (inputs_2 diag)
    {
        const float* xg = x + (size_t)bbase * 64;
        for (int idx = tid; idx < kBT * 16; idx += kThreads) {
            const int row = idx >> 4, j = idx & 15;
            float4 v = *reinterpret_cast<const float4*>(xg + row * 64 + j * 4);
            if ((node >> 2) == j) {
                float* vv = reinterpret_cast<float*>(&v);
                xi[row] = vv[node & 3];
                vv[node & 3] = 0.0f;
            }
            float4 o = make_float4(f2tf(v.x), f2tf(v.y), f2tf(v.z), f2tf(v.w));
            *reinterpret_cast<float4*>(act + row * kAS + j * 4) = o;
        }
    }
    // BP1: [W1a;W2a] as B[k=n_in][n=h], pre-paired (k, k+4)
    {
        const float* w1 = W1a + (size_t)node * 4096;
        const float* w2 = W2a + (size_t)node * 4096;
        for (int t = tid; t < 1024; t += kThreads) {
            const int h = t >> 3, k8 = t & 7;
            const float* src = (h < 64) ? (w1 + h * 64 + k8 * 8)
                                        : (w2 + (h - 64) * 64 + k8 * 8);
            const float4 lo = *reinterpret_cast<const float4*>(src);
            const float4 hi = *reinterpret_cast<const float4*>(src + 4);
            float2* dst = bp1 + (size_t)(k8 * 128 + h) * 4;
            dst[0] = make_float2(f2tf(lo.x), f2tf(hi.x));
            dst[1] = make_float2(f2tf(lo.y), f2tf(hi.y));
            dst[2] = make_float2(f2tf(lo.z), f2tf(hi.z));
            dst[3] = make_float2(f2tf(lo.w), f2tf(hi.w));
        }
    }
    // BP2: zero-padded concat weight, B[k=h1][n=m] (m<32: W1b over k<64; m>=32: W2b over k>=64)
    {
        const float* wb1 = W1b + (size_t)node * 2048;
        const float* wb2 = W2b + (size_t)node * 2048;
        for (int t = tid; t < 1024; t += kThreads) {
            const int m = t >> 4, k8 = t & 15;
            float2* dst = bp2 + (size_t)(k8 * 64 + m) * 4;
            if ((m < 32) == (k8 < 8)) {
                const float* src = (m < 32) ? (wb1 + m * 64 + k8 * 8)
                                            : (wb2 + (m - 32) * 64 + (k8 - 8) * 8);
                const float4 lo = *reinterpret_cast<const float4*>(src);
                const float4 hi = *reinterpret_cast<const float4*>(src + 4);
                dst[0] = make_float2(f2tf(lo.x), f2tf(hi.x));
                dst[1] = make_float2(f2tf(lo.y), f2tf(hi.y));
                dst[2] = make_float2(f2tf(lo.z), f2tf(hi.z));
                dst[3] = make_float2(f2tf(lo.w), f2tf(hi.w));
            } else {
                const float2 z = make_float2(0.f, 0.f);
                dst[0] = z; dst[1] = z; dst[2] = z; dst[3] = z;
            }
        }
    }
    // BP3: W3a[:,0:64] as B[k=c][n=h]
    {
        const float* w3 = W3a + (size_t)node * 8192;
        for (int t = tid; t < 512; t += kThreads) {
            const int h = t >> 3, k8 = t & 7;
            const float* src = w3 + h * 128 + k8 * 8;
            const float4 lo = *reinterpret_cast<const float4*>(src);
            const float4 hi = *reinterpret_cast<const float4*>(src + 4);
            float2* dst = bp3 + (size_t)(k8 * 64 + h) * 4;
            dst[0] = make_float2(f2tf(lo.x), f2tf(hi.x));
            dst[1] = make_float2(f2tf(lo.y), f2tf(hi.y));
            dst[2] = make_float2(f2tf(lo.z), f2tf(hi.z));
            dst[3] = make_float2(f2tf(lo.w), f2tf(hi.w));
        }
        if (tid < 64) {
            w3x[tid]   = w3[tid * 128 + 64 + node];     // fp32 rank-1 x2 column
            b3a_s[tid] = b3a[node * 64 + tid];
            w3b_s[tid] = W3b[node * 64 + tid];
        }
        if (tid == 0) b3b_s[0] = b3b[node];
    }
    __syncthreads();

    // ---------------- per-warp fused MLP ----------------
    const int wid = tid >> 5, lane = tid & 31;
    const int tg = lane >> 2, t4 = lane & 3;
    const int r0 = wid * 32;

    float acc[2][8][4];

    // L1, upper half first (cols 64..127) so X (cols 0..63) survives for the
    // lower half; lower half's stores land after its own reads.
    warp_gemm<8>(acc, act, r0, bp1, 128, 64, tg, t4);
    store_relu(acc, act, r0, 64, tg, t4);
    warp_gemm<8>(acc, act, r0, bp1, 128, 0, tg, t4);
    store_relu(acc, act, r0, 0, tg, t4);
    __syncwarp();

    // L2: K=128 over H1, 64 outputs -> act cols 0..63
    warp_gemm<16>(acc, act, r0, bp2, 64, 0, tg, t4);
    store_relu(acc, act, r0, 0, tg, t4);
    __syncwarp();

    // L3: K=64 over H2
    warp_gemm<8>(acc, act, r0, bp3, 64, 0, tg, t4);

    // epilogue (fp32): h = relu(D3 + xi*w3x + b3a); out = relu(h.w3b + b3b)
    float s[2][2] = {{0.f, 0.f}, {0.f, 0.f}};
    #pragma unroll
    for (int mt = 0; mt < 2; mt++) {
        const int ru = r0 + 16 * mt + tg;
        const float xu = xi[ru], xl = xi[ru + 8];
        #pragma unroll
        for (int nt = 0; nt < 8; nt++) {
            const int c0 = 8 * nt + 2 * t4;
            const float wx0 = w3x[c0], wx1 = w3x[c0 + 1];
            const float ba0 = b3a_s[c0], ba1 = b3a_s[c0 + 1];
            const float wb0 = w3b_s[c0], wb1 = w3b_s[c0 + 1];
            s[mt][0] += fmaxf(acc[mt][nt][0] + xu * wx0 + ba0, 0.f) * wb0
                      + fmaxf(acc[mt][nt][1] + xu * wx1 + ba1, 0.f) * wb1;
            s[mt][1] += fmaxf(acc[mt][nt][2] + xl * wx0 + ba0, 0.f) * wb0
                      + fmaxf(acc[mt][nt][3] + xl * wx1 + ba1, 0.f) * wb1;
        }
    }
    const float bb = b3b_s[0];
    #pragma unroll
    for (int mt = 0; mt < 2; mt++) {
        #pragma unroll
        for (int half = 0; half < 2; half++) {
            float v = s[mt][half];
            v += __shfl_xor_sync(0xffffffff, v, 1);
            v += __shfl_xor_sync(0xffffffff, v, 2);
            if (t4 == 0) {
                const int ru = r0 + 16 * mt + tg + 8 * half;
                out[(size_t)(bbase + ru) * 64 + node] = fmaxf(v + bb, 0.f);
            }
        }
    }
}

extern "C" void kernel_launch(void* const* d_in, const int* in_sizes, int n_in,
                              void* d_out, int out_size)
{
    (void)in_sizes; (void)n_in; (void)out_size;
    const float* x   = (const float*)d_in[0];
    const float* W1a = (const float*)d_in[1];
    const float* W1b = (const float*)d_in[2];
    const float* W2a = (const float*)d_in[3];
    const float* W2b = (const float*)d_in[4];
    const float* W3a = (const float*)d_in[5];
    const float* b3a = (const float*)d_in[6];
    const float* W3b = (const float*)d_in[7];
    const float* b3b = (const float*)d_in[8];
    float* out = (float*)d_out;

    cudaFuncSetAttribute(ctp_mma_kernel,
                         cudaFuncAttributeMaxDynamicSharedMemorySize,
                         (int)SMEM_BYTES);
    dim3 grid(kB / kBT, 64);   // 64 batch tiles x 64 nodes
    ctp_mma_kernel<<<grid, kThreads, SMEM_BYTES>>>(
        x, W1a, W1b, W2a, W2b, W3a, b3a, W3b, b3b, out);
}

// round 4
// speedup vs baseline: 5.1485x; 1.7258x over previous
#include <cuda_runtime.h>
#include <cuda_bf16.h>
#include <cstdint>

// CausalTrajectoryPrediction: fused 3-GEMM MLP via mma.sync m16n8k16 bf16
// + ldmatrix (portable PTX; tcgen05 unavailable under .target sm_103).
// Block = (node, 256 batch rows), 8 warps; each warp owns 32 rows end-to-end.
// Activations bf16 in smem (stride 136 elems = 272B -> conflict-free ldmatrix
// & STS). Accumulation + epilogue fp32. ~104KB smem -> 2 blocks/SM.

namespace {
constexpr int kB       = 16384;
constexpr int kBT      = 256;
constexpr int kThreads = 256;
constexpr int kAS      = 136;    // act stride in bf16 elems (272 B)

constexpr uint32_t OFF_ACT = 0;          // bf16 [256][136] = 69632
constexpr uint32_t OFF_BP1 = 69632;      // uint2 [4][128][4] = 16384
constexpr uint32_t OFF_BP2 = 86016;      // uint2 [2][4][32][4] = 8192
constexpr uint32_t OFF_BP3 = 94208;      // uint2 [4][64][4] = 8192
constexpr uint32_t OFF_XI  = 102400;     // float [256]
constexpr uint32_t OFF_W3X = 103424;     // float [64]
constexpr uint32_t OFF_B3A = 103680;     // float [64]
constexpr uint32_t OFF_W3B = 103936;     // float [64]
constexpr uint32_t OFF_B3B = 104192;     // float
constexpr uint32_t SMEM_BYTES = 104448;
} // namespace

__device__ __forceinline__ uint32_t smem_u32(const void* p) {
    uint32_t a;
    asm("{ .reg .u64 t; cvta.to.shared.u64 t, %1; cvt.u32.u64 %0, t; }"
        : "=r"(a) : "l"(p));
    return a;
}
__device__ __forceinline__ uint32_t bf2(float a, float b) {
    __nv_bfloat162 h = __floats2bfloat162_rn(a, b);   // x=a(low), y=b(high)
    return *reinterpret_cast<uint32_t*>(&h);
}
__device__ __forceinline__ void ldmat4(uint32_t r[4], uint32_t saddr) {
    asm volatile("ldmatrix.sync.aligned.m8n8.x4.shared.b16 {%0,%1,%2,%3}, [%4];"
                 : "=r"(r[0]), "=r"(r[1]), "=r"(r[2]), "=r"(r[3]) : "r"(saddr));
}
__device__ __forceinline__ void mma16(float d[4], const uint32_t a[4], uint2 b) {
    asm volatile(
        "mma.sync.aligned.m16n8k16.row.col.f32.bf16.bf16.f32 "
        "{%0,%1,%2,%3}, {%4,%5,%6,%7}, {%8,%9}, {%0,%1,%2,%3};"
        : "+f"(d[0]), "+f"(d[1]), "+f"(d[2]), "+f"(d[3])
        : "r"(a[0]), "r"(a[1]), "r"(a[2]), "r"(a[3]), "r"(b.x), "r"(b.y));
}

// Warp GEMM: 32 rows x (NT*8) cols, K = 16*KSTEPS.
// a_base: lane-specific ldmatrix addr for (row tile 0, kstep 0) incl. kbase.
// bp: pre-offset by n0; layout uint2[s][nstride][4]; lane picks +lane within
//     each 32-entry n-tile block (contiguous 256B -> conflict-free LDS.64).
template <int KSTEPS, int NT>
__device__ __forceinline__ void wgemm(float acc[2][8][4], uint32_t a_base,
                                      const uint2* bp, int nstride, int lane) {
    #pragma unroll
    for (int mt = 0; mt < 2; mt++)
        #pragma unroll
        for (int nt = 0; nt < NT; nt++)
            #pragma unroll
            for (int i = 0; i < 4; i++) acc[mt][nt][i] = 0.0f;

    #pragma unroll
    for (int s = 0; s < KSTEPS; s++) {
        uint32_t a0[4], a1[4];
        ldmat4(a0, a_base + s * 32);                 // rows r0..r0+15
        ldmat4(a1, a_base + s * 32 + 16 * 272);      // rows r0+16..r0+31
        const uint2* bs = bp + (size_t)s * nstride * 4 + lane;
        #pragma unroll
        for (int nt = 0; nt < NT; nt++) {
            const uint2 bv = bs[nt * 32];
            mma16(acc[0][nt], a0, bv);
            mma16(acc[1][nt], a1, bv);
        }
    }
}

template <int NT>
__device__ __forceinline__ void store_relu(const float acc[2][8][4],
                                           __nv_bfloat16* act, int r0,
                                           int cbase, int tg, int t4) {
    #pragma unroll
    for (int mt = 0; mt < 2; mt++) {
        const int ru = r0 + mt * 16 + tg;
        #pragma unroll
        for (int nt = 0; nt < NT; nt++) {
            const int c = cbase + nt * 8 + 2 * t4;
            *reinterpret_cast<uint32_t*>(act + ru * kAS + c) =
                bf2(fmaxf(acc[mt][nt][0], 0.f), fmaxf(acc[mt][nt][1], 0.f));
            *reinterpret_cast<uint32_t*>(act + (ru + 8) * kAS + c) =
                bf2(fmaxf(acc[mt][nt][2], 0.f), fmaxf(acc[mt][nt][3], 0.f));
        }
    }
}

__global__ void __launch_bounds__(kThreads, 2)
ctp_bf16_kernel(const float* __restrict__ x,
                const float* __restrict__ W1a, const float* __restrict__ W1b,
                const float* __restrict__ W2a, const float* __restrict__ W2b,
                const float* __restrict__ W3a, const float* __restrict__ b3a,
                const float* __restrict__ W3b, const float* __restrict__ b3b,
                float* __restrict__ out)
{
    extern __shared__ char smem[];
    __nv_bfloat16* act = reinterpret_cast<__nv_bfloat16*>(smem + OFF_ACT);
    uint2* bp1 = reinterpret_cast<uint2*>(smem + OFF_BP1);
    uint2* bp2 = reinterpret_cast<uint2*>(smem + OFF_BP2);
    uint2* bp3 = reinterpret_cast<uint2*>(smem + OFF_BP3);
    float* xi    = reinterpret_cast<float*>(smem + OFF_XI);
    float* w3x   = reinterpret_cast<float*>(smem + OFF_W3X);
    float* b3a_s = reinterpret_cast<float*>(smem + OFF_B3A);
    float* w3b_s = reinterpret_cast<float*>(smem + OFF_W3B);
    float* b3b_s = reinterpret_cast<float*>(smem + OFF_B3B);

    const int tid   = threadIdx.x;
    const int node  = blockIdx.y;
    const int bbase = blockIdx.x * kBT;

    // ---------------- staging ----------------
    // X: mask col `node` (inputs_1), save fp32 x[:,node] (inputs_2 diagonal)
    {
        const float* xg = x + (size_t)bbase * 64;
        for (int idx = tid; idx < kBT * 16; idx += kThreads) {
            const int row = idx >> 4, j = idx & 15;
            float4 v = *reinterpret_cast<const float4*>(xg + row * 64 + j * 4);
            if ((node >> 2) == j) {
                float* vv = reinterpret_cast<float*>(&v);
                xi[row] = vv[node & 3];
                vv[node & 3] = 0.0f;
            }
            *reinterpret_cast<uint2*>(act + row * kAS + j * 4) =
                make_uint2(bf2(v.x, v.y), bf2(v.z, v.w));
        }
    }
    // BP1: [W1a;W2a] as B[n=h 0..127][k=0..63], frag-paired:
    // entry[s][n][t4] = {pair(k=16s+2t4), pair(k=16s+8+2t4)}
    {
        const float* w1 = W1a + (size_t)node * 4096;
        const float* w2 = W2a + (size_t)node * 4096;
        for (int t = tid; t < 512; t += kThreads) {
            const int n = t >> 2, s = t & 3;
            const float* src = (n < 64) ? (w1 + n * 64 + s * 16)
                                        : (w2 + (n - 64) * 64 + s * 16);
            uint2* dst = bp1 + (size_t)(s * 128 + n) * 4;
            #pragma unroll
            for (int t4 = 0; t4 < 4; t4++)
                dst[t4] = make_uint2(bf2(src[2 * t4],     src[2 * t4 + 1]),
                                     bf2(src[2 * t4 + 8], src[2 * t4 + 9]));
        }
    }
    // BP2 compact: branch0 = W1b (H1 cols 0..63), branch1 = W2b (cols 64..127)
    {
        for (int t = tid; t < 256; t += kThreads) {
            const int br = t >> 7, rem = t & 127, m = rem >> 2, s = rem & 3;
            const float* src = (br ? W2b : W1b) + (size_t)node * 2048 + m * 64 + s * 16;
            uint2* dst = bp2 + (size_t)((br * 4 + s) * 32 + m) * 4;
            #pragma unroll
            for (int t4 = 0; t4 < 4; t4++)
                dst[t4] = make_uint2(bf2(src[2 * t4],     src[2 * t4 + 1]),
                                     bf2(src[2 * t4 + 8], src[2 * t4 + 9]));
        }
    }
    // BP3: W3a[:,0:64] as B[n=h][k=c]
    {
        const float* w3 = W3a + (size_t)node * 8192;
        for (int t = tid; t < 256; t += kThreads) {
            const int n = t >> 2, s = t & 3;
            const float* src = w3 + n * 128 + s * 16;
            uint2* dst = bp3 + (size_t)(s * 64 + n) * 4;
            #pragma unroll
            for (int t4 = 0; t4 < 4; t4++)
                dst[t4] = make_uint2(bf2(src[2 * t4],     src[2 * t4 + 1]),
                                     bf2(src[2 * t4 + 8], src[2 * t4 + 9]));
        }
        if (tid < 64) {
            w3x[tid]   = w3[tid * 128 + 64 + node];
            b3a_s[tid] = b3a[node * 64 + tid];
            w3b_s[tid] = W3b[node * 64 + tid];
        }
        if (tid == 0) b3b_s[0] = b3b[node];
    }
    __syncthreads();

    // ---------------- per-warp fused MLP ----------------
    const int wid = tid >> 5, lane = tid & 31;
    const int tg = lane >> 2, t4 = lane & 3;
    const int r0 = wid * 32;

    // lane-specific ldmatrix base: mat = lane>>3
    //   mat0: rows+0..7 klo | mat1: rows+8..15 klo | mat2/3: khi (+8 elems)
    const int mat = lane >> 3, rin = lane & 7;
    const int arow = ((mat & 1) << 3) + rin;
    const int akb  = ((mat >> 1) << 3) * 2;            // bytes
    const uint32_t act_u32 = smem_u32(act);
    const uint32_t a_base0 = act_u32 + (uint32_t)(r0 + arow) * 272 + akb;

    float acc[2][8][4];

    // L1 (K=64): upper output cols 64..127 first, so X (cols 0..63) survives
    wgemm<4, 8>(acc, a_base0, bp1 + 64 * 4, 128, lane);
    store_relu<8>(acc, act, r0, 64, tg, t4);
    __syncwarp();
    wgemm<4, 8>(acc, a_base0, bp1, 128, lane);
    store_relu<8>(acc, act, r0, 0, tg, t4);
    __syncwarp();

    // L2 (two compact 32-col GEMMs, K=64 each)
    wgemm<4, 4>(acc, a_base0, bp2, 32, lane);              // branch1: A cols 0..63
    store_relu<4>(acc, act, r0, 0, tg, t4);
    __syncwarp();
    wgemm<4, 4>(acc, a_base0 + 64 * 2, bp2 + 512, 32, lane); // branch2: A cols 64..127
    store_relu<4>(acc, act, r0, 32, tg, t4);
    __syncwarp();

    // L3 (K=64, 64 outputs) -> keep in registers
    wgemm<4, 8>(acc, a_base0, bp3, 64, lane);

    // epilogue (fp32): h = relu(D3 + xi*w3x + b3a); out = relu(h.w3b + b3b)
    float s[2][2] = {{0.f, 0.f}, {0.f, 0.f}};
    #pragma unroll
    for (int mt = 0; mt < 2; mt++) {
        const int ru = r0 + 16 * mt + tg;
        const float xu = xi[ru], xl = xi[ru + 8];
        #pragma unroll
        for (int nt = 0; nt < 8; nt++) {
            const int c0 = 8 * nt + 2 * t4;
            const float wx0 = w3x[c0], wx1 = w3x[c0 + 1];
            const float ba0 = b3a_s[c0], ba1 = b3a_s[c0 + 1];
            const float wb0 = w3b_s[c0], wb1 = w3b_s[c0 + 1];
            s[mt][0] += fmaxf(acc[mt][nt][0] + xu * wx0 + ba0, 0.f) * wb0
                      + fmaxf(acc[mt][nt][1] + xu * wx1 + ba1, 0.f) * wb1;
            s[mt][1] += fmaxf(acc[mt][nt][2] + xl * wx0 + ba0, 0.f) * wb0
                      + fmaxf(acc[mt][nt][3] + xl * wx1 + ba1, 0.f) * wb1;
        }
    }
    const float bb = b3b_s[0];
    #pragma unroll
    for (int mt = 0; mt < 2; mt++)
        #pragma unroll
        for (int half = 0; half < 2; half++) {
            float v = s[mt][half];
            v += __shfl_xor_sync(0xffffffff, v, 1);
            v += __shfl_xor_sync(0xffffffff, v, 2);
            if (t4 == 0) {
                const int ru = r0 + 16 * mt + tg + 8 * half;
                out[(size_t)(bbase + ru) * 64 + node] = fmaxf(v + bb, 0.f);
            }
        }
}

extern "C" void kernel_launch(void* const* d_in, const int* in_sizes, int n_in,
                              void* d_out, int out_size)
{
    (void)in_sizes; (void)n_in; (void)out_size;
    const float* x   = (const float*)d_in[0];
    const float* W1a = (const float*)d_in[1];
    const float* W1b = (const float*)d_in[2];
    const float* W2a = (const float*)d_in[3];
    const float* W2b = (const float*)d_in[4];
    const float* W3a = (const float*)d_in[5];
    const float* b3a = (const float*)d_in[6];
    const float* W3b = (const float*)d_in[7];
    const float* b3b = (const float*)d_in[8];
    float* out = (float*)d_out;

    cudaFuncSetAttribute(ctp_bf16_kernel,
                         cudaFuncAttributeMaxDynamicSharedMemorySize,
                         (int)SMEM_BYTES);
    dim3 grid(kB / kBT, 64);
    ctp_bf16_kernel<<<grid, kThreads, SMEM_BYTES>>>(
        x, W1a, W1b, W2a, W2b, W3a, b3a, W3b, b3b, out);
}

// round 5
// speedup vs baseline: 5.5030x; 1.0689x over previous
#include <cuda_runtime.h>
#include <cuda_bf16.h>
#include <cstdint>

// CausalTrajectoryPrediction: fused 3-GEMM MLP, mma.sync m16n8k16 bf16 with
// IN-REGISTER fragment chaining: the C-fragment layout of one layer is packed
// (relu + bf16x2) directly into the A-fragment layout of the next layer —
// no inter-layer smem traffic, no ldmatrix after L1, no block syncs after
// staging. Block = (node, 256 batch rows), 8 warps x 32 rows each.

namespace {
constexpr int kB       = 16384;
constexpr int kBT      = 256;
constexpr int kThreads = 256;
constexpr int kXS      = 72;     // X row stride in bf16 elems (144 B)

constexpr uint32_t OFF_X   = 0;          // bf16 [256][72] = 36864
constexpr uint32_t OFF_BP1 = 36864;      // uint2 [4][128][4] = 16384
constexpr uint32_t OFF_BP2 = 53248;      // uint2 [2][4][32][4] = 8192
constexpr uint32_t OFF_BP3 = 61440;      // uint2 [4][64][4] = 8192
constexpr uint32_t OFF_XI  = 69632;      // float [256]
constexpr uint32_t OFF_W3X = 70656;      // float [64]
constexpr uint32_t OFF_B3A = 70912;      // float [64]
constexpr uint32_t OFF_W3B = 71168;      // float [64]
constexpr uint32_t OFF_B3B = 71424;      // float
constexpr uint32_t SMEM_BYTES = 71440;
} // namespace

__device__ __forceinline__ uint32_t smem_u32(const void* p) {
    uint32_t a;
    asm("{ .reg .u64 t; cvta.to.shared.u64 t, %1; cvt.u32.u64 %0, t; }"
        : "=r"(a) : "l"(p));
    return a;
}
__device__ __forceinline__ uint32_t bf2(float a, float b) {
    __nv_bfloat162 h = __floats2bfloat162_rn(a, b);
    return *reinterpret_cast<uint32_t*>(&h);
}
__device__ __forceinline__ void ldmat4(uint32_t r[4], uint32_t saddr) {
    asm volatile("ldmatrix.sync.aligned.m8n8.x4.shared.b16 {%0,%1,%2,%3}, [%4];"
                 : "=r"(r[0]), "=r"(r[1]), "=r"(r[2]), "=r"(r[3]) : "r"(saddr));
}
__device__ __forceinline__ void mma16(float d[4], const uint32_t a[4], uint2 b) {
    asm volatile(
        "mma.sync.aligned.m16n8k16.row.col.f32.bf16.bf16.f32 "
        "{%0,%1,%2,%3}, {%4,%5,%6,%7}, {%8,%9}, {%0,%1,%2,%3};"
        : "+f"(d[0]), "+f"(d[1]), "+f"(d[2]), "+f"(d[3])
        : "r"(a[0]), "r"(a[1]), "r"(a[2]), "r"(a[3]), "r"(b.x), "r"(b.y));
}
// relu + pack two adjacent C tiles (cols 16s..16s+7 | 16s+8..16s+15) into the
// next layer's A fragment for kstep s.
__device__ __forceinline__ void pack2(uint32_t a[4], const float c0[4],
                                      const float c1[4]) {
    a[0] = bf2(fmaxf(c0[0], 0.f), fmaxf(c0[1], 0.f));
    a[1] = bf2(fmaxf(c0[2], 0.f), fmaxf(c0[3], 0.f));
    a[2] = bf2(fmaxf(c1[0], 0.f), fmaxf(c1[1], 0.f));
    a[3] = bf2(fmaxf(c1[2], 0.f), fmaxf(c1[3], 0.f));
}

// L1 warp GEMM: A via ldmatrix from X (stride 144B), NT=8 n-tiles, K=64.
__device__ __forceinline__ void l1gemm(float acc[2][8][4], uint32_t a_base,
                                       const uint2* __restrict__ bp, int lane) {
    #pragma unroll
    for (int mt = 0; mt < 2; mt++)
        #pragma unroll
        for (int nt = 0; nt < 8; nt++)
            #pragma unroll
            for (int i = 0; i < 4; i++) acc[mt][nt][i] = 0.0f;
    #pragma unroll
    for (int s = 0; s < 4; s++) {
        uint32_t a0[4], a1[4];
        ldmat4(a0, a_base + s * 32);
        ldmat4(a1, a_base + s * 32 + 16 * 144);
        const uint2* bs = bp + (size_t)s * 128 * 4 + lane;
        #pragma unroll
        for (int nt = 0; nt < 8; nt++) {
            const uint2 bv = bs[nt * 32];
            mma16(acc[0][nt], a0, bv);
            mma16(acc[1][nt], a1, bv);
        }
    }
}

// Register-A warp GEMM: A frags in registers, NT n-tiles, KS ksteps.
template <int NT, int KS>
__device__ __forceinline__ void rgemm(float acc[2][NT][4],
                                      const uint32_t a[2][KS][4],
                                      const uint2* __restrict__ bp,
                                      int nstride, int lane) {
    #pragma unroll
    for (int mt = 0; mt < 2; mt++)
        #pragma unroll
        for (int nt = 0; nt < NT; nt++)
            #pragma unroll
            for (int i = 0; i < 4; i++) acc[mt][nt][i] = 0.0f;
    #pragma unroll
    for (int s = 0; s < KS; s++) {
        const uint2* bs = bp + (size_t)s * nstride * 4 + lane;
        #pragma unroll
        for (int nt = 0; nt < NT; nt++) {
            const uint2 bv = bs[nt * 32];
            mma16(acc[0][nt], a[0][s], bv);
            mma16(acc[1][nt], a[1][s], bv);
        }
    }
}

__global__ void __launch_bounds__(kThreads, 2)
ctp_chain_kernel(const float* __restrict__ x,
                 const float* __restrict__ W1a, const float* __restrict__ W1b,
                 const float* __restrict__ W2a, const float* __restrict__ W2b,
                 const float* __restrict__ W3a, const float* __restrict__ b3a,
                 const float* __restrict__ W3b, const float* __restrict__ b3b,
                 float* __restrict__ out)
{
    extern __shared__ char smem[];
    __nv_bfloat16* Xs = reinterpret_cast<__nv_bfloat16*>(smem + OFF_X);
    uint2* bp1 = reinterpret_cast<uint2*>(smem + OFF_BP1);
    uint2* bp2 = reinterpret_cast<uint2*>(smem + OFF_BP2);
    uint2* bp3 = reinterpret_cast<uint2*>(smem + OFF_BP3);
    float* xi    = reinterpret_cast<float*>(smem + OFF_XI);
    float* w3x   = reinterpret_cast<float*>(smem + OFF_W3X);
    float* b3a_s = reinterpret_cast<float*>(smem + OFF_B3A);
    float* w3b_s = reinterpret_cast<float*>(smem + OFF_W3B);
    float* b3b_s = reinterpret_cast<float*>(smem + OFF_B3B);

    const int tid   = threadIdx.x;
    const int node  = blockIdx.y;
    const int bbase = blockIdx.x * kBT;

    // ---------------- staging ----------------
    {   // X: mask col `node`, save fp32 x[:,node]
        const float* xg = x + (size_t)bbase * 64;
        for (int idx = tid; idx < kBT * 16; idx += kThreads) {
            const int row = idx >> 4, j = idx & 15;
            float4 v = *reinterpret_cast<const float4*>(xg + row * 64 + j * 4);
            if ((node >> 2) == j) {
                float* vv = reinterpret_cast<float*>(&v);
                xi[row] = vv[node & 3];
                vv[node & 3] = 0.0f;
            }
            *reinterpret_cast<uint2*>(Xs + row * kXS + j * 4) =
                make_uint2(bf2(v.x, v.y), bf2(v.z, v.w));
        }
    }
    {   // BP1: [W1a;W2a] as B[n=h 0..127][k], frag-paired
        const float* w1 = W1a + (size_t)node * 4096;
        const float* w2 = W2a + (size_t)node * 4096;
        for (int t = tid; t < 512; t += kThreads) {
            const int n = t >> 2, s = t & 3;
            const float* src = (n < 64) ? (w1 + n * 64 + s * 16)
                                        : (w2 + (n - 64) * 64 + s * 16);
            uint2* dst = bp1 + (size_t)(s * 128 + n) * 4;
            #pragma unroll
            for (int t4 = 0; t4 < 4; t4++)
                dst[t4] = make_uint2(bf2(src[2 * t4],     src[2 * t4 + 1]),
                                     bf2(src[2 * t4 + 8], src[2 * t4 + 9]));
        }
    }
    {   // BP2 compact: br0 = W1b (k = H1 cols 0..63), br1 = W2b (cols 64..127)
        for (int t = tid; t < 256; t += kThreads) {
            const int br = t >> 7, rem = t & 127, m = rem >> 2, s = rem & 3;
            const float* src = (br ? W2b : W1b) + (size_t)node * 2048 + m * 64 + s * 16;
            uint2* dst = bp2 + (size_t)((br * 4 + s) * 32 + m) * 4;
            #pragma unroll
            for (int t4 = 0; t4 < 4; t4++)
                dst[t4] = make_uint2(bf2(src[2 * t4],     src[2 * t4 + 1]),
                                     bf2(src[2 * t4 + 8], src[2 * t4 + 9]));
        }
    }
    {   // BP3: W3a[:,0:64] as B[n=h][k=c]
        const float* w3 = W3a + (size_t)node * 8192;
        for (int t = tid; t < 256; t += kThreads) {
            const int n = t >> 2, s = t & 3;
            const float* src = w3 + n * 128 + s * 16;
            uint2* dst = bp3 + (size_t)(s * 64 + n) * 4;
            #pragma unroll
            for (int t4 = 0; t4 < 4; t4++)
                dst[t4] = make_uint2(bf2(src[2 * t4],     src[2 * t4 + 1]),
                                     bf2(src[2 * t4 + 8], src[2 * t4 + 9]));
        }
        if (tid < 64) {
            w3x[tid]   = w3[tid * 128 + 64 + node];
            b3a_s[tid] = b3a[node * 64 + tid];
            w3b_s[tid] = W3b[node * 64 + tid];
        }
        if (tid == 0) b3b_s[0] = b3b[node];
    }
    __syncthreads();

    // ---------------- per-warp register-chained MLP ----------------
    const int wid = tid >> 5, lane = tid & 31;
    const int tg = lane >> 2, t4 = lane & 3;
    const int r0 = wid * 32;

    // ldmatrix lane base for X (stride 144B)
    const int mat = lane >> 3, rin = lane & 7;
    const int arow = ((mat & 1) << 3) + rin;
    const int akb  = (mat >> 1) << 4;                    // 0 or 16 bytes
    const uint32_t a_base0 = smem_u32(Xs) + (uint32_t)(r0 + arow) * 144 + akb;

    float acc[2][8][4];          // big accumulator (L1 halves, L3)
    float acc4[2][4][4];         // L2 accumulator
    uint32_t A2[2][4][4];        // one L1-half's packed output (A of L2)
    uint32_t A3[2][4][4];        // packed H2 (A of L3)

    // L1 half0 (H1 cols 0..63) -> A2
    l1gemm(acc, a_base0, bp1, lane);
    #pragma unroll
    for (int mt = 0; mt < 2; mt++)
        #pragma unroll
        for (int s = 0; s < 4; s++)
            pack2(A2[mt][s], acc[mt][2 * s], acc[mt][2 * s + 1]);

    // L2 branch0 (W1b over H1 cols 0..63) -> A3 ksteps 0,1
    rgemm<4, 4>(acc4, A2, bp2, 32, lane);
    #pragma unroll
    for (int mt = 0; mt < 2; mt++)
        #pragma unroll
        for (int s = 0; s < 2; s++)
            pack2(A3[mt][s], acc4[mt][2 * s], acc4[mt][2 * s + 1]);

    // L1 half1 (H1 cols 64..127) -> A2 (reuse)
    l1gemm(acc, a_base0, bp1 + 64 * 4, lane);
    #pragma unroll
    for (int mt = 0; mt < 2; mt++)
        #pragma unroll
        for (int s = 0; s < 4; s++)
            pack2(A2[mt][s], acc[mt][2 * s], acc[mt][2 * s + 1]);

    // L2 branch1 (W2b over H1 cols 64..127) -> A3 ksteps 2,3
    rgemm<4, 4>(acc4, A2, bp2 + 512, 32, lane);
    #pragma unroll
    for (int mt = 0; mt < 2; mt++)
        #pragma unroll
        for (int s = 0; s < 2; s++)
            pack2(A3[mt][2 + s], acc4[mt][2 * s], acc4[mt][2 * s + 1]);

    // L3 (K=64, 64 outputs) -> acc
    rgemm<8, 4>(acc, A3, bp3, 64, lane);

    // epilogue (fp32): h = relu(D3 + xi*w3x + b3a); out = relu(h.w3b + b3b)
    float s2[2][2] = {{0.f, 0.f}, {0.f, 0.f}};
    #pragma unroll
    for (int mt = 0; mt < 2; mt++) {
        const int ru = r0 + 16 * mt + tg;
        const float xu = xi[ru], xl = xi[ru + 8];
        #pragma unroll
        for (int nt = 0; nt < 8; nt++) {
            const int c0 = 8 * nt + 2 * t4;
            const float wx0 = w3x[c0], wx1 = w3x[c0 + 1];
            const float ba0 = b3a_s[c0], ba1 = b3a_s[c0 + 1];
            const float wb0 = w3b_s[c0], wb1 = w3b_s[c0 + 1];
            s2[mt][0] += fmaxf(acc[mt][nt][0] + xu * wx0 + ba0, 0.f) * wb0
                       + fmaxf(acc[mt][nt][1] + xu * wx1 + ba1, 0.f) * wb1;
            s2[mt][1] += fmaxf(acc[mt][nt][2] + xl * wx0 + ba0, 0.f) * wb0
                       + fmaxf(acc[mt][nt][3] + xl * wx1 + ba1, 0.f) * wb1;
        }
    }
    const float bb = b3b_s[0];
    #pragma unroll
    for (int mt = 0; mt < 2; mt++)
        #pragma unroll
        for (int half = 0; half < 2; half++) {
            float v = s2[mt][half];
            v += __shfl_xor_sync(0xffffffff, v, 1);
            v += __shfl_xor_sync(0xffffffff, v, 2);
            if (t4 == 0) {
                const int ru = r0 + 16 * mt + tg + 8 * half;
                out[(size_t)(bbase + ru) * 64 + node] = fmaxf(v + bb, 0.f);
            }
        }
}

extern "C" void kernel_launch(void* const* d_in, const int* in_sizes, int n_in,
                              void* d_out, int out_size)
{
    (void)in_sizes; (void)n_in; (void)out_size;
    const float* x   = (const float*)d_in[0];
    const float* W1a = (const float*)d_in[1];
    const float* W1b = (const float*)d_in[2];
    const float* W2a = (const float*)d_in[3];
    const float* W2b = (const float*)d_in[4];
    const float* W3a = (const float*)d_in[5];
    const float* b3a = (const float*)d_in[6];
    const float* W3b = (const float*)d_in[7];
    const float* b3b = (const float*)d_in[8];
    float* out = (float*)d_out;

    cudaFuncSetAttribute(ctp_chain_kernel,
                         cudaFuncAttributeMaxDynamicSharedMemorySize,
                         (int)SMEM_BYTES);
    dim3 grid(kB / kBT, 64);
    ctp_chain_kernel<<<grid, kThreads, SMEM_BYTES>>>(
        x, W1a, W1b, W2a, W2b, W3a, b3a, W3b, b3b, out);
}